// round 11
// baseline (speedup 1.0000x reference)
#include <cuda_runtime.h>
#include <cuda_bf16.h>

#define T_LEN 128
#define BATCH 512
#define DIN   768

typedef unsigned long long ull;
typedef unsigned int uint32;

// ---------------- scratch (static device arrays; no allocation) ----------------
static __device__ float g_xproj[T_LEN * BATCH * 64];   // bi-LSTM gate pre-activations (x part + bias)
static __device__ float g_h[T_LEN * BATCH * 16];       // concat(h_f, h_b)
static __device__ float g_z[T_LEN * BATCH * 16];       // ptr-LSTM hidden states
static __device__ __nv_bfloat16 g_Wbh[64 * DIN];       // bf16-hi of combined weight, [n][k]
static __device__ __nv_bfloat16 g_Wbl[64 * DIN];       // bf16-lo residual, [n][k]
static __device__ float g_bc[64];                      // combined bias

// ---------------- helpers ----------------
__device__ __forceinline__ float ex2f(float x) {
    float r; asm("ex2.approx.ftz.f32 %0, %1;" : "=f"(r) : "f"(x)); return r;
}
__device__ __forceinline__ float rcpf(float x) {
    float r; asm("rcp.approx.ftz.f32 %0, %1;" : "=f"(r) : "f"(x)); return r;
}
__device__ __forceinline__ float sigf(float x) {
    return __fdividef(1.f, 1.f + __expf(-x));
}
__device__ __forceinline__ float tanhf_fast(float x) {
    float e = __expf(2.f * x);
    return 1.f - __fdividef(2.f, e + 1.f);
}
// f32x2 packed math
__device__ __forceinline__ ull fma2(ull a, ull b, ull c) {
    ull d; asm("fma.rn.f32x2 %0, %1, %2, %3;" : "=l"(d) : "l"(a), "l"(b), "l"(c)); return d;
}
__device__ __forceinline__ ull pack2(float x, float y) {
    ull d; asm("mov.b64 %0, {%1, %2};" : "=l"(d) : "f"(x), "f"(y)); return d;
}
__device__ __forceinline__ float2 unpack2(ull v) {
    float2 r; asm("mov.b64 {%0, %1}, %2;" : "=f"(r.x), "=f"(r.y) : "l"(v)); return r;
}
// pack two f32 -> bf16x2 (first arg -> low half)
__device__ __forceinline__ uint32 packbf(float lo, float hi) {
    uint32 r; asm("cvt.rn.bf16x2.f32 %0, %1, %2;" : "=r"(r) : "f"(hi), "f"(lo)); return r;
}
__device__ __forceinline__ float bflo(uint32 p) { return __uint_as_float(p << 16); }
__device__ __forceinline__ float bfhi(uint32 p) { return __uint_as_float(p & 0xffff0000u); }

__device__ __forceinline__ uint32 smem_u32(const void* p) {
    uint32 a;
    asm("{ .reg .u64 t; cvta.to.shared.u64 t, %1; cvt.u32.u64 %0, t; }" : "=r"(a) : "l"(p));
    return a;
}
__device__ __forceinline__ void ldsm_x4(uint32& r0, uint32& r1, uint32& r2, uint32& r3, uint32 addr) {
    asm volatile("ldmatrix.sync.aligned.m8n8.x4.shared.b16 {%0,%1,%2,%3}, [%4];"
                 : "=r"(r0), "=r"(r1), "=r"(r2), "=r"(r3) : "r"(addr));
}

// bf16 mma m16n8k16, row.col, f32 accumulate
__device__ __forceinline__ void mma_bf16(float* d, const uint32* a, const uint32* b) {
    asm volatile(
        "mma.sync.aligned.m16n8k16.row.col.f32.bf16.bf16.f32 "
        "{%0,%1,%2,%3}, {%4,%5,%6,%7}, {%8,%9}, {%0,%1,%2,%3};"
        : "+f"(d[0]), "+f"(d[1]), "+f"(d[2]), "+f"(d[3])
        : "r"(a[0]), "r"(a[1]), "r"(a[2]), "r"(a[3]), "r"(b[0]), "r"(b[1]));
}

// ---------------- K0: build combined weight, bf16 hi/lo, transposed [n][k] ----------------
__global__ __launch_bounds__(256) void k_prep(
    const float* __restrict__ Wih_f, const float* __restrict__ Wih_b,
    const float* __restrict__ bih_f, const float* __restrict__ bhh_f,
    const float* __restrict__ bih_b, const float* __restrict__ bhh_b)
{
    int n = blockIdx.y;
    int k = blockIdx.x * 256 + threadIdx.x;
    float w = (n < 32) ? Wih_f[n * DIN + k] : Wih_b[(n - 32) * DIN + k];
    __nv_bfloat16 hi = __float2bfloat16_rn(w);
    float res = w - __bfloat162float(hi);
    g_Wbh[n * DIN + k] = hi;
    g_Wbl[n * DIN + k] = __float2bfloat16_rn(res);
    if (blockIdx.x == 0 && blockIdx.y == 0 && threadIdx.x < 64) {
        int i = threadIdx.x;
        g_bc[i] = (i < 32) ? (bih_f[i] + bhh_f[i]) : (bih_b[i - 32] + bhh_b[i - 32]);
    }
}

// ---------------- K1: xproj = X (65536x768) @ Wc (768x64) + bc  (bf16 mma + ldmatrix) ----------------
#define XPITCH 40   // bf16 pitch -> 80-byte rows: 16B-aligned, ldmatrix conflict-free
__global__ __launch_bounds__(256, 2) void k_gemm_xproj(const float* __restrict__ X)
{
    __shared__ alignas(16) __nv_bfloat16 Xh[128 * XPITCH];
    __shared__ alignas(16) __nv_bfloat16 Xl[128 * XPITCH];
    __shared__ alignas(16) __nv_bfloat16 Wh[64 * XPITCH];
    __shared__ alignas(16) __nv_bfloat16 Wl[64 * XPITCH];

    const int tid = threadIdx.x;
    const int rowBase = blockIdx.x * 128;
    const int w = tid >> 5;
    const int lane = tid & 31;
    const int g = lane >> 2;
    const int t4 = lane & 3;

    const int sel = lane >> 3;
    const int rowA = w * 16 + (sel & 1) * 8 + (lane & 7);
    const int colA = (sel >> 1) * 16;
    const int rowB = (sel >> 1) * 8 + (lane & 7);
    const int colB = (sel & 1) * 16;
    const uint32 aHi = smem_u32(Xh) + rowA * 80 + colA;
    const uint32 aLo = smem_u32(Xl) + rowA * 80 + colA;
    const uint32 bHi = smem_u32(Wh) + rowB * 80 + colB;
    const uint32 bLo = smem_u32(Wl) + rowB * 80 + colB;

    float acc[8][4];
#pragma unroll
    for (int nt = 0; nt < 8; nt++)
#pragma unroll
        for (int q = 0; q < 4; q++) acc[nt][q] = 0.f;

    float4 vx[4];
    ull vwh[2], vwl[2];

#pragma unroll
    for (int i = 0; i < 4; i++) {
        int idx = i * 256 + tid;
        int r = idx >> 3, k4 = (idx & 7) * 4;
        vx[i] = *(const float4*)(X + (size_t)(rowBase + r) * DIN + k4);
    }
#pragma unroll
    for (int i = 0; i < 2; i++) {
        int idx = i * 256 + tid;
        int n = idx >> 3, k8 = (idx & 7) * 4;
        vwh[i] = *(const ull*)(g_Wbh + n * DIN + k8);
        vwl[i] = *(const ull*)(g_Wbl + n * DIN + k8);
    }

    for (int c = 0; c < 24; c++) {
#pragma unroll
        for (int i = 0; i < 4; i++) {
            int idx = i * 256 + tid;
            int r = idx >> 3, k4 = (idx & 7) * 4;
            float4 v = vx[i];
            __nv_bfloat16 hx = __float2bfloat16_rn(v.x);
            __nv_bfloat16 hy = __float2bfloat16_rn(v.y);
            __nv_bfloat16 hz = __float2bfloat16_rn(v.z);
            __nv_bfloat16 hw = __float2bfloat16_rn(v.w);
            *(__nv_bfloat162*)&Xh[r * XPITCH + k4 + 0] = __nv_bfloat162(hx, hy);
            *(__nv_bfloat162*)&Xh[r * XPITCH + k4 + 2] = __nv_bfloat162(hz, hw);
            *(__nv_bfloat162*)&Xl[r * XPITCH + k4 + 0] = __nv_bfloat162(
                __float2bfloat16_rn(v.x - __bfloat162float(hx)),
                __float2bfloat16_rn(v.y - __bfloat162float(hy)));
            *(__nv_bfloat162*)&Xl[r * XPITCH + k4 + 2] = __nv_bfloat162(
                __float2bfloat16_rn(v.z - __bfloat162float(hz)),
                __float2bfloat16_rn(v.w - __bfloat162float(hw)));
        }
#pragma unroll
        for (int i = 0; i < 2; i++) {
            int idx = i * 256 + tid;
            int n = idx >> 3, k8 = (idx & 7) * 4;
            *(ull*)&Wh[n * XPITCH + k8] = vwh[i];
            *(ull*)&Wl[n * XPITCH + k8] = vwl[i];
        }
        __syncthreads();

        if (c < 23) {
            int k0 = (c + 1) * 32;
#pragma unroll
            for (int i = 0; i < 4; i++) {
                int idx = i * 256 + tid;
                int r = idx >> 3, k4 = (idx & 7) * 4;
                vx[i] = *(const float4*)(X + (size_t)(rowBase + r) * DIN + k0 + k4);
            }
#pragma unroll
            for (int i = 0; i < 2; i++) {
                int idx = i * 256 + tid;
                int n = idx >> 3, k8 = (idx & 7) * 4;
                vwh[i] = *(const ull*)(g_Wbh + n * DIN + k0 + k8);
                vwl[i] = *(const ull*)(g_Wbl + n * DIN + k0 + k8);
            }
        }

#pragma unroll
        for (int ks = 0; ks < 2; ks++) {
            uint32 ah[4], al[4];
            ldsm_x4(ah[0], ah[1], ah[2], ah[3], aHi + ks * 32);
            ldsm_x4(al[0], al[1], al[2], al[3], aLo + ks * 32);
#pragma unroll
            for (int p = 0; p < 4; p++) {
                uint32 bh[4], bl[4];
                ldsm_x4(bh[0], bh[1], bh[2], bh[3], bHi + p * 1280 + ks * 32);
                ldsm_x4(bl[0], bl[1], bl[2], bl[3], bLo + p * 1280 + ks * 32);
                mma_bf16(acc[2 * p], ah, bh);
                mma_bf16(acc[2 * p], ah, bl);
                mma_bf16(acc[2 * p], al, bh);
                mma_bf16(acc[2 * p + 1], ah, bh + 2);
                mma_bf16(acc[2 * p + 1], ah, bl + 2);
                mma_bf16(acc[2 * p + 1], al, bh + 2);
            }
        }
        __syncthreads();
    }

    const int r0 = rowBase + w * 16 + g;
#pragma unroll
    for (int nt = 0; nt < 8; nt++) {
        int cbase = nt * 8 + 2 * t4;
        float b0 = g_bc[cbase], b1 = g_bc[cbase + 1];
        *(float2*)(g_xproj + (size_t)r0 * 64 + cbase) = make_float2(acc[nt][0] + b0, acc[nt][1] + b1);
        *(float2*)(g_xproj + (size_t)(r0 + 8) * 64 + cbase) = make_float2(acc[nt][2] + b0, acc[nt][3] + b1);
    }
}

// ---------------- K2: bi-LSTM scan — 16 threads per (item,dir), shfl broadcast, 1-MUFU acts ----------------
// Thread (l16) owns gate rows: row_a = hi*8+jj (i|f), row_b = 16+hi*8+jj (g|o).
// Weights prescaled by log2e (sigmoid rows) / 2*log2e (tanh rows).
__global__ __launch_bounds__(128) void k_bilstm(
    const float* __restrict__ Whh_f, const float* __restrict__ Whh_b)
{
    const int tid = threadIdx.x;
    const int l = tid & 31;
    const int sub = l >> 4;                 // item-dir within warp (0/1)
    const int l16 = l & 15;
    const int jj = l16 & 7, hi = l16 >> 3;
    const int itemdir = blockIdx.x * 8 + (tid >> 5) * 2 + sub;   // 0..1023
    const int dir = itemdir >> 9;
    const int b = itemdir & 511;
    const float* Whh = dir ? Whh_b : Whh_f;
    const float L2E = 1.4426950408889634f;
    const float sc_a = L2E;
    const float sc_b = hi ? L2E : 2.f * L2E;
    const int row_a = hi * 8 + jj;
    const int row_b = 16 + hi * 8 + jj;

    ull wha[4], whb[4];
#pragma unroll
    for (int m = 0; m < 4; m++) {
        const float* ra_ = Whh + row_a * 8;
        const float* rb_ = Whh + row_b * 8;
        wha[m] = pack2(ra_[2 * m] * sc_a, ra_[2 * m + 1] * sc_a);
        whb[m] = pack2(rb_[2 * m] * sc_b, rb_[2 * m + 1] * sc_b);
    }

    float c = 0.f, h = 0.f;
    const int base = sub * 16;

    int t0 = dir ? 127 : 0;
    int t1 = dir ? 126 : 1;
    const float* xp0 = g_xproj + ((size_t)t0 * BATCH + b) * 64 + dir * 32;
    const float* xp1 = g_xproj + ((size_t)t1 * BATCH + b) * 64 + dir * 32;
    float na = xp0[row_a] * sc_a, nb = xp0[row_b] * sc_b;
    float ma = xp1[row_a] * sc_a, mb = xp1[row_b] * sc_b;

    for (int s = 0; s < T_LEN; s++) {
        int t = dir ? (127 - s) : s;
        float qa = na, qb = nb;
        na = ma; nb = mb;
        if (s < T_LEN - 2) {
            int tn = dir ? (125 - s) : (s + 2);
            const float* xn = g_xproj + ((size_t)tn * BATCH + b) * 64 + dir * 32;
            ma = xn[row_a] * sc_a; mb = xn[row_b] * sc_b;
        }
        // gather h (lives on hi=0 lanes of this item-dir) as 4 f32x2 pairs
        ull hp[4];
#pragma unroll
        for (int m = 0; m < 4; m++) {
            float h0 = __shfl_sync(0xffffffffu, h, base + 2 * m);
            float h1 = __shfl_sync(0xffffffffu, h, base + 2 * m + 1);
            hp[m] = pack2(h0, h1);
        }
        ull s0 = pack2(qa, 0.f), s1 = 0ULL, u0 = pack2(qb, 0.f), u1 = 0ULL;
        s0 = fma2(wha[0], hp[0], s0); s1 = fma2(wha[1], hp[1], s1);
        u0 = fma2(whb[0], hp[0], u0); u1 = fma2(whb[1], hp[1], u1);
        s0 = fma2(wha[2], hp[2], s0); s1 = fma2(wha[3], hp[3], s1);
        u0 = fma2(whb[2], hp[2], u0); u1 = fma2(whb[3], hp[3], u1);
        float2 A0 = unpack2(s0), A1 = unpack2(s1), B0 = unpack2(u0), B1 = unpack2(u1);
        float pa = (A0.x + A0.y) + (A1.x + A1.y);
        float pb = (B0.x + B0.y) + (B1.x + B1.y);
        float ra = rcpf(1.f + ex2f(-pa));                 // sigmoid (i|f)
        float rb = rcpf(1.f + ex2f(-pb));
        float act_b = hi ? rb : (2.f * rb - 1.f);         // o | tanh(g)
        float fv = __shfl_sync(0xffffffffu, ra, base + 8 + jj);
        float ov = __shfl_sync(0xffffffffu, act_b, base + 8 + jj);
        c = fv * c + ra * act_b;                          // valid on hi==0 lanes
        float th = 2.f * rcpf(1.f + ex2f(-c * (2.f * L2E))) - 1.f;
        h = ov * th;
        if (hi == 0) g_h[(size_t)t * 8192 + b * 16 + dir * 8 + jj] = h;
    }
}

// ---------------- K3: ptr-LSTM scan — 32 threads/item, fused input projection ----------------
// Thread l owns rows: row_a = hi*16+jj (i|f), row_b = 32+hi*16+jj (g|o). x-part for t+1
// computed in the shadow after h(t); h gathered via 16 independent shfls.
__global__ __launch_bounds__(128) void k_ptrlstm(
    const float* __restrict__ Wih_p, const float* __restrict__ Whh_p,
    const float* __restrict__ bih_p, const float* __restrict__ bhh_p)
{
    __shared__ float xs[T_LEN * 64];   // [t*64 + warp*16 + e]

    const int tid = threadIdx.x;
    const int w = tid >> 5, l = tid & 31;
    const int jj = l & 15, hi = l >> 4;
    const int bbase = blockIdx.x * 4;
    const int b = bbase + w;

    for (int i = tid; i < 2048; i += 128) {
        int t = i >> 4, rem = i & 15;
        int item = rem >> 2, f4 = rem & 3;
        float4 v = *(const float4*)(g_h + (size_t)t * 8192 + (bbase + item) * 16 + f4 * 4);
        *(float4*)&xs[t * 64 + item * 16 + f4 * 4] = v;
    }

    const float L2E = 1.4426950408889634f;
    const float sc_a = L2E;
    const float sc_b = hi ? L2E : 2.f * L2E;
    const int row_a = hi * 16 + jj;
    const int row_b = 32 + hi * 16 + jj;

    ull wxa[8], wha[8], wxb[8], whb[8];
    {
        const float* wia = Wih_p + row_a * 16;
        const float* wra = Whh_p + row_a * 16;
        const float* wib = Wih_p + row_b * 16;
        const float* wrb = Whh_p + row_b * 16;
#pragma unroll
        for (int m = 0; m < 8; m++) {
            wxa[m] = pack2(wia[2 * m] * sc_a, wia[2 * m + 1] * sc_a);
            wha[m] = pack2(wra[2 * m] * sc_a, wra[2 * m + 1] * sc_a);
            wxb[m] = pack2(wib[2 * m] * sc_b, wib[2 * m + 1] * sc_b);
            whb[m] = pack2(wrb[2 * m] * sc_b, wrb[2 * m + 1] * sc_b);
        }
    }
    const float ba = (bih_p[row_a] + bhh_p[row_a]) * sc_a;
    const float bb = (bih_p[row_b] + bhh_p[row_b]) * sc_b;

    float c = 0.f, h = 0.f;
    __syncthreads();

    // x-part for step 0
    ull xaa, xab;
    {
        const ull* xr = (const ull*)&xs[w * 16];
        ull s0 = pack2(ba, 0.f), s1 = 0ULL, u0 = pack2(bb, 0.f), u1 = 0ULL;
#pragma unroll
        for (int m = 0; m < 8; m += 2) {
            s0 = fma2(wxa[m], xr[m], s0); s1 = fma2(wxa[m + 1], xr[m + 1], s1);
            u0 = fma2(wxb[m], xr[m], u0); u1 = fma2(wxb[m + 1], xr[m + 1], u1);
        }
        xaa = fma2(pack2(1.f, 1.f), s1, s0);
        xab = fma2(pack2(1.f, 1.f), u1, u0);
    }

    for (int t = 0; t < T_LEN; t++) {
        // gather h (lanes 0..15) as 8 f32x2 pairs — independent shfls
        ull hp[8];
#pragma unroll
        for (int m = 0; m < 8; m++) {
            float h0 = __shfl_sync(0xffffffffu, h, 2 * m);
            float h1 = __shfl_sync(0xffffffffu, h, 2 * m + 1);
            hp[m] = pack2(h0, h1);
        }
        ull s0 = xaa, s1 = 0ULL, u0 = xab, u1 = 0ULL;
#pragma unroll
        for (int m = 0; m < 8; m += 2) {
            s0 = fma2(wha[m], hp[m], s0); s1 = fma2(wha[m + 1], hp[m + 1], s1);
            u0 = fma2(whb[m], hp[m], u0); u1 = fma2(whb[m + 1], hp[m + 1], u1);
        }
        float2 A0 = unpack2(s0), A1 = unpack2(s1), B0 = unpack2(u0), B1 = unpack2(u1);
        float pa = (A0.x + A0.y) + (A1.x + A1.y);
        float pb = (B0.x + B0.y) + (B1.x + B1.y);
        float ra = rcpf(1.f + ex2f(-pa));                 // sigmoid (i|f)
        float rb = rcpf(1.f + ex2f(-pb));
        float act_b = hi ? rb : (2.f * rb - 1.f);         // o | tanh(g)
        float fv = __shfl_sync(0xffffffffu, ra, jj + 16);
        float ov = __shfl_sync(0xffffffffu, act_b, jj + 16);
        c = fv * c + ra * act_b;                          // valid on hi==0 lanes
        float th = 2.f * rcpf(1.f + ex2f(-c * (2.f * L2E))) - 1.f;
        h = ov * th;
        if (hi == 0) g_z[(size_t)t * 8192 + b * 16 + jj] = h;

        // shadow: x-part for t+1
        if (t < T_LEN - 1) {
            const ull* xr = (const ull*)&xs[(t + 1) * 64 + w * 16];
            ull a0 = pack2(ba, 0.f), a1 = 0ULL, b0 = pack2(bb, 0.f), b1 = 0ULL;
#pragma unroll
            for (int m = 0; m < 8; m += 2) {
                a0 = fma2(wxa[m], xr[m], a0); a1 = fma2(wxa[m + 1], xr[m + 1], a1);
                b0 = fma2(wxb[m], xr[m], b0); b1 = fma2(wxb[m + 1], xr[m + 1], b1);
            }
            xaa = fma2(pack2(1.f, 1.f), a1, a0);
            xab = fma2(pack2(1.f, 1.f), b1, b0);
        }
    }
}

// ---------------- K4: tensor-core attention + output head, one CTA per t ----------------
#define HP 20
#define HTP 516
#define OFF_HHI   0
#define OFF_HLO   20480
#define OFF_ZHI   40960
#define OFF_ZLO   61440
#define OFF_HT    81920
#define OFF_CP    114944
#define OFF_INV   117248
#define OFF_CTX   117376
#define OFF_WH    152192
#define OFF_WE    153216
#define OFF_WV    154240
#define ATT_SMEM  154304

__global__ __launch_bounds__(512, 1) void k_attn(
    const float* __restrict__ W_h, const float* __restrict__ W_e,
    const float* __restrict__ W_v, float* __restrict__ out)
{
    extern __shared__ char smc[];
    __nv_bfloat16* hhi = (__nv_bfloat16*)(smc + OFF_HHI);
    __nv_bfloat16* hlo = (__nv_bfloat16*)(smc + OFF_HLO);
    __nv_bfloat16* zhi = (__nv_bfloat16*)(smc + OFF_ZHI);
    __nv_bfloat16* zlo = (__nv_bfloat16*)(smc + OFF_ZLO);
    float* hT   = (float*)(smc + OFF_HT);
    float* cp   = (float*)(smc + OFF_CP);
    float* invs = (float*)(smc + OFF_INV);
    float* ctx  = (float*)(smc + OFF_CTX);
    float* sWh  = (float*)(smc + OFF_WH);
    float* sWe  = (float*)(smc + OFF_WE);
    float* sWv  = (float*)(smc + OFF_WV);

    const int t = blockIdx.x, tid = threadIdx.x;
    const int w = tid >> 5, lane = tid & 31;
    const int qr = lane >> 2, qc = lane & 3;
    const float LOG2E = 1.4426950408889634f;

    const float4* hg = (const float4*)(g_h + (size_t)t * 8192);
    const float4* zg = (const float4*)(g_z + (size_t)t * 8192);
#pragma unroll
    for (int it = 0; it < 4; it++) {
        int i = it * 512 + tid;
        int r = i >> 2, d4 = (i & 3) * 4;
        float4 v = hg[i];
        uint32 h01 = packbf(v.x, v.y), h23 = packbf(v.z, v.w);
        *(uint32*)&hhi[r * HP + d4]     = h01;
        *(uint32*)&hhi[r * HP + d4 + 2] = h23;
        *(uint32*)&hlo[r * HP + d4]     = packbf(v.x - bflo(h01), v.y - bfhi(h01));
        *(uint32*)&hlo[r * HP + d4 + 2] = packbf(v.z - bflo(h23), v.w - bfhi(h23));
        hT[(d4 + 0) * HTP + r] = v.x;
        hT[(d4 + 1) * HTP + r] = v.y;
        hT[(d4 + 2) * HTP + r] = v.z;
        hT[(d4 + 3) * HTP + r] = v.w;
        float4 u = zg[i];
        u.x *= LOG2E; u.y *= LOG2E; u.z *= LOG2E; u.w *= LOG2E;
        uint32 z01 = packbf(u.x, u.y), z23 = packbf(u.z, u.w);
        *(uint32*)&zhi[r * HP + d4]     = z01;
        *(uint32*)&zhi[r * HP + d4 + 2] = z23;
        *(uint32*)&zlo[r * HP + d4]     = packbf(u.x - bflo(z01), u.y - bfhi(z01));
        *(uint32*)&zlo[r * HP + d4 + 2] = packbf(u.z - bflo(z23), u.w - bfhi(z23));
    }
    if (tid < 256) { sWh[tid] = W_h[tid]; sWe[tid] = W_e[tid]; }
    if (tid < 16)  sWv[tid] = W_v[tid];
    __syncthreads();

    uint32 Ahh[2][4], Ahl[2][4];
#pragma unroll
    for (int mt = 0; mt < 2; mt++) {
        int row = 32 * w + 16 * mt + qr;
        int base = row * HP + 2 * qc;
        Ahh[mt][0] = *(const uint32*)&hhi[base];
        Ahh[mt][1] = *(const uint32*)&hhi[base + 8 * HP];
        Ahh[mt][2] = *(const uint32*)&hhi[base + 8];
        Ahh[mt][3] = *(const uint32*)&hhi[base + 8 * HP + 8];
        Ahl[mt][0] = *(const uint32*)&hlo[base];
        Ahl[mt][1] = *(const uint32*)&hlo[base + 8 * HP];
        Ahl[mt][2] = *(const uint32*)&hlo[base + 8];
        Ahl[mt][3] = *(const uint32*)&hlo[base + 8 * HP + 8];
    }

    float ctxacc[2][2][4];
#pragma unroll
    for (int mt = 0; mt < 2; mt++)
#pragma unroll
        for (int nt = 0; nt < 2; nt++)
#pragma unroll
            for (int q = 0; q < 4; q++) ctxacc[mt][nt][q] = 0.f;

    for (int tile = 0; tile < 16; tile++) {
        const int c0 = tile * 32;
        uint32 Aeh[2][2][4], Ael[2][2][4];

#pragma unroll
        for (int nt = 0; nt < 4; nt++) {
            int crow = c0 + 8 * nt + qr;
            int zb = crow * HP + 2 * qc;
            uint32 bzh[2], bzl[2];
            bzh[0] = *(const uint32*)&zhi[zb];
            bzh[1] = *(const uint32*)&zhi[zb + 8];
            bzl[0] = *(const uint32*)&zlo[zb];
            bzl[1] = *(const uint32*)&zlo[zb + 8];
            float P0 = 0.f, P1 = 0.f;
            const int ks = nt >> 1, hf = nt & 1;
#pragma unroll
            for (int mt = 0; mt < 2; mt++) {
                float S[4] = {0.f, 0.f, 0.f, 0.f};
                mma_bf16(S, Ahh[mt], bzh);
                mma_bf16(S, Ahh[mt], bzl);
                mma_bf16(S, Ahl[mt], bzh);
                float e0 = ex2f(S[0]), e1 = ex2f(S[1]), e2 = ex2f(S[2]), e3 = ex2f(S[3]);
                P0 += e0 + e2; P1 += e1 + e3;
                uint32 p01 = packbf(e0, e1), p23 = packbf(e2, e3);
                Aeh[mt][ks][2 * hf]     = p01;
                Aeh[mt][ks][2 * hf + 1] = p23;
                Ael[mt][ks][2 * hf]     = packbf(e0 - bflo(p01), e1 - bfhi(p01));
                Ael[mt][ks][2 * hf + 1] = packbf(e2 - bflo(p23), e3 - bfhi(p23));
            }
            P0 += __shfl_xor_sync(0xffffffffu, P0, 4);
            P0 += __shfl_xor_sync(0xffffffffu, P0, 8);
            P0 += __shfl_xor_sync(0xffffffffu, P0, 16);
            P1 += __shfl_xor_sync(0xffffffffu, P1, 4);
            P1 += __shfl_xor_sync(0xffffffffu, P1, 8);
            P1 += __shfl_xor_sync(0xffffffffu, P1, 16);
            if (qr == 0) {
                cp[w * 36 + 8 * nt + 2 * qc]     = P0;
                cp[w * 36 + 8 * nt + 2 * qc + 1] = P1;
            }
        }
        __syncthreads();
        if (tid < 32) {
            float s = 0.f;
#pragma unroll
            for (int ww = 0; ww < 16; ww++) s += cp[ww * 36 + tid];
            invs[tid] = __fdividef(1.f, s);
        }
        __syncthreads();

#pragma unroll
        for (int ks = 0; ks < 2; ks++) {
#pragma unroll
            for (int nt2 = 0; nt2 < 2; nt2++) {
                int d = 8 * nt2 + qr;
                int cc = 16 * ks + 2 * qc;
                float i0 = invs[cc], i1 = invs[cc + 1], i8 = invs[cc + 8], i9 = invs[cc + 9];
                const float* hr = hT + d * HTP + c0 + cc;
                float v0 = hr[0] * i0, v1 = hr[1] * i1, v8 = hr[8] * i8, v9 = hr[9] * i9;
                uint32 bh[2], bl[2];
                bh[0] = packbf(v0, v1);
                bh[1] = packbf(v8, v9);
                bl[0] = packbf(v0 - bflo(bh[0]), v1 - bfhi(bh[0]));
                bl[1] = packbf(v8 - bflo(bh[1]), v9 - bfhi(bh[1]));
#pragma unroll
                for (int mt = 0; mt < 2; mt++) {
                    mma_bf16(ctxacc[mt][nt2], Aeh[mt][ks], bh);
                    mma_bf16(ctxacc[mt][nt2], Ael[mt][ks], bh);
                    mma_bf16(ctxacc[mt][nt2], Aeh[mt][ks], bl);
                }
            }
        }
    }

#pragma unroll
    for (int mt = 0; mt < 2; mt++)
#pragma unroll
        for (int nt2 = 0; nt2 < 2; nt2++) {
            int row = 32 * w + 16 * mt + qr;
            int col = 8 * nt2 + 2 * qc;
            ctx[row * 17 + col]           = ctxacc[mt][nt2][0];
            ctx[row * 17 + col + 1]       = ctxacc[mt][nt2][1];
            ctx[(row + 8) * 17 + col]     = ctxacc[mt][nt2][2];
            ctx[(row + 8) * 17 + col + 1] = ctxacc[mt][nt2][3];
        }
    __syncthreads();

    {
        int b = tid;
        float hb2[16], cx[16];
        const float4* hp4 = (const float4*)(g_h + (size_t)t * 8192 + b * 16);
#pragma unroll
        for (int q = 0; q < 4; q++) {
            float4 v = hp4[q];
            hb2[4 * q + 0] = v.x; hb2[4 * q + 1] = v.y; hb2[4 * q + 2] = v.z; hb2[4 * q + 3] = v.w;
        }
#pragma unroll
        for (int k = 0; k < 16; k++) cx[k] = ctx[b * 17 + k];
        float pv = 0.f;
#pragma unroll
        for (int r = 0; r < 16; r++) {
            float a = 0.f;
#pragma unroll
            for (int k = 0; k < 16; k++)
                a += sWh[r * 16 + k] * hb2[k] + sWe[r * 16 + k] * cx[k];
            pv += sWv[r] * tanhf_fast(a);
        }
        out[(size_t)t * BATCH + b] = sigf(pv);
    }
}

// ---------------- launch ----------------
extern "C" void kernel_launch(void* const* d_in, const int* in_sizes, int n_in,
                              void* d_out, int out_size)
{
    const float* X     = (const float*)d_in[0];
    const float* Wih_f = (const float*)d_in[1];
    const float* Whh_f = (const float*)d_in[2];
    const float* bih_f = (const float*)d_in[3];
    const float* bhh_f = (const float*)d_in[4];
    const float* Wih_b = (const float*)d_in[5];
    const float* Whh_b = (const float*)d_in[6];
    const float* bih_b = (const float*)d_in[7];
    const float* bhh_b = (const float*)d_in[8];
    const float* Wih_p = (const float*)d_in[9];
    const float* Whh_p = (const float*)d_in[10];
    const float* bih_p = (const float*)d_in[11];
    const float* bhh_p = (const float*)d_in[12];
    const float* W_h   = (const float*)d_in[13];
    const float* W_e   = (const float*)d_in[14];
    const float* W_v   = (const float*)d_in[15];
    float* out = (float*)d_out;

    cudaFuncSetAttribute((const void*)k_attn, cudaFuncAttributeMaxDynamicSharedMemorySize, 160 * 1024);

    k_prep<<<dim3(3, 64), 256>>>(Wih_f, Wih_b, bih_f, bhh_f, bih_b, bhh_b);
    k_gemm_xproj<<<(T_LEN * BATCH) / 128, 256>>>(X);
    k_bilstm<<<128, 128>>>(Whh_f, Whh_b);
    k_ptrlstm<<<128, 128>>>(Wih_p, Whh_p, bih_p, bhh_p);
    k_attn<<<T_LEN, 512, ATT_SMEM>>>(W_h, W_e, W_v, out);
}

// round 12
// speedup vs baseline: 1.0417x; 1.0417x over previous
#include <cuda_runtime.h>
#include <cuda_bf16.h>

#define T_LEN 128
#define BATCH 512
#define DIN   768

typedef unsigned long long ull;
typedef unsigned int uint32;

// ---------------- scratch (static device arrays; no allocation) ----------------
static __device__ float g_xproj[T_LEN * BATCH * 64];   // bi-LSTM gate pre-activations (x part + bias)
static __device__ float g_h[T_LEN * BATCH * 16];       // concat(h_f, h_b)
static __device__ float g_z[T_LEN * BATCH * 16];       // ptr-LSTM hidden states
static __device__ __nv_bfloat16 g_Wbh[64 * DIN];       // bf16-hi of combined weight, [n][k]
static __device__ __nv_bfloat16 g_Wbl[64 * DIN];       // bf16-lo residual, [n][k]
static __device__ float g_bc[64];                      // combined bias

// ---------------- helpers ----------------
__device__ __forceinline__ float ex2f(float x) {
    float r; asm("ex2.approx.ftz.f32 %0, %1;" : "=f"(r) : "f"(x)); return r;
}
__device__ __forceinline__ float rcpf(float x) {
    float r; asm("rcp.approx.ftz.f32 %0, %1;" : "=f"(r) : "f"(x)); return r;
}
__device__ __forceinline__ float sigf(float x) {
    return __fdividef(1.f, 1.f + __expf(-x));
}
__device__ __forceinline__ float tanhf_fast(float x) {
    float e = __expf(2.f * x);
    return 1.f - __fdividef(2.f, e + 1.f);
}
// f32x2 packed math
__device__ __forceinline__ ull fma2(ull a, ull b, ull c) {
    ull d; asm("fma.rn.f32x2 %0, %1, %2, %3;" : "=l"(d) : "l"(a), "l"(b), "l"(c)); return d;
}
__device__ __forceinline__ ull pack2(float x, float y) {
    ull d; asm("mov.b64 %0, {%1, %2};" : "=l"(d) : "f"(x), "f"(y)); return d;
}
__device__ __forceinline__ float2 unpack2(ull v) {
    float2 r; asm("mov.b64 {%0, %1}, %2;" : "=f"(r.x), "=f"(r.y) : "l"(v)); return r;
}
// pack two f32 -> bf16x2 (first arg -> low half)
__device__ __forceinline__ uint32 packbf(float lo, float hi) {
    uint32 r; asm("cvt.rn.bf16x2.f32 %0, %1, %2;" : "=r"(r) : "f"(hi), "f"(lo)); return r;
}
__device__ __forceinline__ float bflo(uint32 p) { return __uint_as_float(p << 16); }
__device__ __forceinline__ float bfhi(uint32 p) { return __uint_as_float(p & 0xffff0000u); }

__device__ __forceinline__ uint32 smem_u32(const void* p) {
    uint32 a;
    asm("{ .reg .u64 t; cvta.to.shared.u64 t, %1; cvt.u32.u64 %0, t; }" : "=r"(a) : "l"(p));
    return a;
}
__device__ __forceinline__ void ldsm_x4(uint32& r0, uint32& r1, uint32& r2, uint32& r3, uint32 addr) {
    asm volatile("ldmatrix.sync.aligned.m8n8.x4.shared.b16 {%0,%1,%2,%3}, [%4];"
                 : "=r"(r0), "=r"(r1), "=r"(r2), "=r"(r3) : "r"(addr));
}

// bf16 mma m16n8k16, row.col, f32 accumulate
__device__ __forceinline__ void mma_bf16(float* d, const uint32* a, const uint32* b) {
    asm volatile(
        "mma.sync.aligned.m16n8k16.row.col.f32.bf16.bf16.f32 "
        "{%0,%1,%2,%3}, {%4,%5,%6,%7}, {%8,%9}, {%0,%1,%2,%3};"
        : "+f"(d[0]), "+f"(d[1]), "+f"(d[2]), "+f"(d[3])
        : "r"(a[0]), "r"(a[1]), "r"(a[2]), "r"(a[3]), "r"(b[0]), "r"(b[1]));
}

// ---------------- K0: build combined weight, bf16 hi/lo, transposed [n][k] ----------------
__global__ __launch_bounds__(256) void k_prep(
    const float* __restrict__ Wih_f, const float* __restrict__ Wih_b,
    const float* __restrict__ bih_f, const float* __restrict__ bhh_f,
    const float* __restrict__ bih_b, const float* __restrict__ bhh_b)
{
    int n = blockIdx.y;
    int k = blockIdx.x * 256 + threadIdx.x;
    float w = (n < 32) ? Wih_f[n * DIN + k] : Wih_b[(n - 32) * DIN + k];
    __nv_bfloat16 hi = __float2bfloat16_rn(w);
    float res = w - __bfloat162float(hi);
    g_Wbh[n * DIN + k] = hi;
    g_Wbl[n * DIN + k] = __float2bfloat16_rn(res);
    if (blockIdx.x == 0 && blockIdx.y == 0 && threadIdx.x < 64) {
        int i = threadIdx.x;
        g_bc[i] = (i < 32) ? (bih_f[i] + bhh_f[i]) : (bih_b[i - 32] + bhh_b[i - 32]);
    }
}

// ---------------- K1: xproj = X (65536x768) @ Wc (768x64) + bc  (bf16 mma + ldmatrix) ----------------
#define XPITCH 40   // bf16 pitch -> 80-byte rows: 16B-aligned, ldmatrix conflict-free
__global__ __launch_bounds__(256, 2) void k_gemm_xproj(const float* __restrict__ X)
{
    __shared__ alignas(16) __nv_bfloat16 Xh[128 * XPITCH];
    __shared__ alignas(16) __nv_bfloat16 Xl[128 * XPITCH];
    __shared__ alignas(16) __nv_bfloat16 Wh[64 * XPITCH];
    __shared__ alignas(16) __nv_bfloat16 Wl[64 * XPITCH];

    const int tid = threadIdx.x;
    const int rowBase = blockIdx.x * 128;
    const int w = tid >> 5;
    const int lane = tid & 31;
    const int g = lane >> 2;
    const int t4 = lane & 3;

    const int sel = lane >> 3;
    const int rowA = w * 16 + (sel & 1) * 8 + (lane & 7);
    const int colA = (sel >> 1) * 16;
    const int rowB = (sel >> 1) * 8 + (lane & 7);
    const int colB = (sel & 1) * 16;
    const uint32 aHi = smem_u32(Xh) + rowA * 80 + colA;
    const uint32 aLo = smem_u32(Xl) + rowA * 80 + colA;
    const uint32 bHi = smem_u32(Wh) + rowB * 80 + colB;
    const uint32 bLo = smem_u32(Wl) + rowB * 80 + colB;

    float acc[8][4];
#pragma unroll
    for (int nt = 0; nt < 8; nt++)
#pragma unroll
        for (int q = 0; q < 4; q++) acc[nt][q] = 0.f;

    float4 vx[4];
    ull vwh[2], vwl[2];

#pragma unroll
    for (int i = 0; i < 4; i++) {
        int idx = i * 256 + tid;
        int r = idx >> 3, k4 = (idx & 7) * 4;
        vx[i] = *(const float4*)(X + (size_t)(rowBase + r) * DIN + k4);
    }
#pragma unroll
    for (int i = 0; i < 2; i++) {
        int idx = i * 256 + tid;
        int n = idx >> 3, k8 = (idx & 7) * 4;
        vwh[i] = *(const ull*)(g_Wbh + n * DIN + k8);
        vwl[i] = *(const ull*)(g_Wbl + n * DIN + k8);
    }

    for (int c = 0; c < 24; c++) {
#pragma unroll
        for (int i = 0; i < 4; i++) {
            int idx = i * 256 + tid;
            int r = idx >> 3, k4 = (idx & 7) * 4;
            float4 v = vx[i];
            __nv_bfloat16 hx = __float2bfloat16_rn(v.x);
            __nv_bfloat16 hy = __float2bfloat16_rn(v.y);
            __nv_bfloat16 hz = __float2bfloat16_rn(v.z);
            __nv_bfloat16 hw = __float2bfloat16_rn(v.w);
            *(__nv_bfloat162*)&Xh[r * XPITCH + k4 + 0] = __nv_bfloat162(hx, hy);
            *(__nv_bfloat162*)&Xh[r * XPITCH + k4 + 2] = __nv_bfloat162(hz, hw);
            *(__nv_bfloat162*)&Xl[r * XPITCH + k4 + 0] = __nv_bfloat162(
                __float2bfloat16_rn(v.x - __bfloat162float(hx)),
                __float2bfloat16_rn(v.y - __bfloat162float(hy)));
            *(__nv_bfloat162*)&Xl[r * XPITCH + k4 + 2] = __nv_bfloat162(
                __float2bfloat16_rn(v.z - __bfloat162float(hz)),
                __float2bfloat16_rn(v.w - __bfloat162float(hw)));
        }
#pragma unroll
        for (int i = 0; i < 2; i++) {
            int idx = i * 256 + tid;
            int n = idx >> 3, k8 = (idx & 7) * 4;
            *(ull*)&Wh[n * XPITCH + k8] = vwh[i];
            *(ull*)&Wl[n * XPITCH + k8] = vwl[i];
        }
        __syncthreads();

        if (c < 23) {
            int k0 = (c + 1) * 32;
#pragma unroll
            for (int i = 0; i < 4; i++) {
                int idx = i * 256 + tid;
                int r = idx >> 3, k4 = (idx & 7) * 4;
                vx[i] = *(const float4*)(X + (size_t)(rowBase + r) * DIN + k0 + k4);
            }
#pragma unroll
            for (int i = 0; i < 2; i++) {
                int idx = i * 256 + tid;
                int n = idx >> 3, k8 = (idx & 7) * 4;
                vwh[i] = *(const ull*)(g_Wbh + n * DIN + k0 + k8);
                vwl[i] = *(const ull*)(g_Wbl + n * DIN + k0 + k8);
            }
        }

#pragma unroll
        for (int ks = 0; ks < 2; ks++) {
            uint32 ah[4], al[4];
            ldsm_x4(ah[0], ah[1], ah[2], ah[3], aHi + ks * 32);
            ldsm_x4(al[0], al[1], al[2], al[3], aLo + ks * 32);
#pragma unroll
            for (int p = 0; p < 4; p++) {
                uint32 bh[4], bl[4];
                ldsm_x4(bh[0], bh[1], bh[2], bh[3], bHi + p * 1280 + ks * 32);
                ldsm_x4(bl[0], bl[1], bl[2], bl[3], bLo + p * 1280 + ks * 32);
                mma_bf16(acc[2 * p], ah, bh);
                mma_bf16(acc[2 * p], ah, bl);
                mma_bf16(acc[2 * p], al, bh);
                mma_bf16(acc[2 * p + 1], ah, bh + 2);
                mma_bf16(acc[2 * p + 1], ah, bl + 2);
                mma_bf16(acc[2 * p + 1], al, bh + 2);
            }
        }
        __syncthreads();
    }

    const int r0 = rowBase + w * 16 + g;
#pragma unroll
    for (int nt = 0; nt < 8; nt++) {
        int cbase = nt * 8 + 2 * t4;
        float b0 = g_bc[cbase], b1 = g_bc[cbase + 1];
        *(float2*)(g_xproj + (size_t)r0 * 64 + cbase) = make_float2(acc[nt][0] + b0, acc[nt][1] + b1);
        *(float2*)(g_xproj + (size_t)(r0 + 8) * 64 + cbase) = make_float2(acc[nt][2] + b0, acc[nt][3] + b1);
    }
}

// ---------------- K2: bi-LSTM scan — 16 threads per (item,dir), 256-thread blocks ----------------
// (2 warps per SMSP so a co-resident recurrence fills chain-stall issue slots)
__global__ __launch_bounds__(256) void k_bilstm(
    const float* __restrict__ Whh_f, const float* __restrict__ Whh_b)
{
    const int tid = threadIdx.x;
    const int l = tid & 31;
    const int sub = l >> 4;                 // item-dir within warp (0/1)
    const int l16 = l & 15;
    const int jj = l16 & 7, hi = l16 >> 3;
    const int itemdir = blockIdx.x * 16 + (tid >> 5) * 2 + sub;   // 0..1023
    const int dir = itemdir >> 9;
    const int b = itemdir & 511;
    const float* Whh = dir ? Whh_b : Whh_f;
    const float L2E = 1.4426950408889634f;
    const float sc_a = L2E;
    const float sc_b = hi ? L2E : 2.f * L2E;
    const int row_a = hi * 8 + jj;
    const int row_b = 16 + hi * 8 + jj;

    ull wha[4], whb[4];
#pragma unroll
    for (int m = 0; m < 4; m++) {
        const float* ra_ = Whh + row_a * 8;
        const float* rb_ = Whh + row_b * 8;
        wha[m] = pack2(ra_[2 * m] * sc_a, ra_[2 * m + 1] * sc_a);
        whb[m] = pack2(rb_[2 * m] * sc_b, rb_[2 * m + 1] * sc_b);
    }

    float c = 0.f, h = 0.f;
    const int base = sub * 16;

    int t0 = dir ? 127 : 0;
    int t1 = dir ? 126 : 1;
    const float* xp0 = g_xproj + ((size_t)t0 * BATCH + b) * 64 + dir * 32;
    const float* xp1 = g_xproj + ((size_t)t1 * BATCH + b) * 64 + dir * 32;
    float na = xp0[row_a] * sc_a, nb = xp0[row_b] * sc_b;
    float ma = xp1[row_a] * sc_a, mb = xp1[row_b] * sc_b;

    for (int s = 0; s < T_LEN; s++) {
        int t = dir ? (127 - s) : s;
        float qa = na, qb = nb;
        na = ma; nb = mb;
        if (s < T_LEN - 2) {
            int tn = dir ? (125 - s) : (s + 2);
            const float* xn = g_xproj + ((size_t)tn * BATCH + b) * 64 + dir * 32;
            ma = xn[row_a] * sc_a; mb = xn[row_b] * sc_b;
        }
        // gather h (lives on hi=0 lanes of this item-dir) as 4 f32x2 pairs
        ull hp[4];
#pragma unroll
        for (int m = 0; m < 4; m++) {
            float h0 = __shfl_sync(0xffffffffu, h, base + 2 * m);
            float h1 = __shfl_sync(0xffffffffu, h, base + 2 * m + 1);
            hp[m] = pack2(h0, h1);
        }
        ull s0 = pack2(qa, 0.f), s1 = 0ULL, u0 = pack2(qb, 0.f), u1 = 0ULL;
        s0 = fma2(wha[0], hp[0], s0); s1 = fma2(wha[1], hp[1], s1);
        u0 = fma2(whb[0], hp[0], u0); u1 = fma2(whb[1], hp[1], u1);
        s0 = fma2(wha[2], hp[2], s0); s1 = fma2(wha[3], hp[3], s1);
        u0 = fma2(whb[2], hp[2], u0); u1 = fma2(whb[3], hp[3], u1);
        float2 A0 = unpack2(s0), A1 = unpack2(s1), B0 = unpack2(u0), B1 = unpack2(u1);
        float pa = (A0.x + A0.y) + (A1.x + A1.y);
        float pb = (B0.x + B0.y) + (B1.x + B1.y);
        float ra = rcpf(1.f + ex2f(-pa));                 // sigmoid (i|f)
        float rb = rcpf(1.f + ex2f(-pb));
        float act_b = hi ? rb : (2.f * rb - 1.f);         // o | tanh(g)
        float fv = __shfl_sync(0xffffffffu, ra, base + 8 + jj);
        float ov = __shfl_sync(0xffffffffu, act_b, base + 8 + jj);
        c = fv * c + ra * act_b;                          // valid on hi==0 lanes
        float th = 2.f * rcpf(1.f + ex2f(-c * (2.f * L2E))) - 1.f;
        h = ov * th;
        if (hi == 0) g_h[(size_t)t * 8192 + b * 16 + dir * 8 + jj] = h;
    }
}

// ---------------- K3: ptr-LSTM scan — 32 threads/item, 8 items per 256-thread block ----------------
// x slab (64KB) staged in dynamic smem; x-part for t+1 computed in the MUFU shadow.
__global__ __launch_bounds__(256) void k_ptrlstm(
    const float* __restrict__ Wih_p, const float* __restrict__ Whh_p,
    const float* __restrict__ bih_p, const float* __restrict__ bhh_p)
{
    extern __shared__ float xs[];      // [t*128 + item*16 + e], 64 KB

    const int tid = threadIdx.x;
    const int w = tid >> 5, l = tid & 31;
    const int jj = l & 15, hi = l >> 4;
    const int bbase = blockIdx.x * 8;
    const int b = bbase + w;

    for (int i = tid; i < 4096; i += 256) {
        int t = i >> 5, rem = i & 31;
        int item = rem >> 2, f4 = rem & 3;
        float4 v = *(const float4*)(g_h + (size_t)t * 8192 + (bbase + item) * 16 + f4 * 4);
        *(float4*)&xs[t * 128 + item * 16 + f4 * 4] = v;
    }

    const float L2E = 1.4426950408889634f;
    const float sc_a = L2E;
    const float sc_b = hi ? L2E : 2.f * L2E;
    const int row_a = hi * 16 + jj;
    const int row_b = 32 + hi * 16 + jj;

    ull wxa[8], wha[8], wxb[8], whb[8];
    {
        const float* wia = Wih_p + row_a * 16;
        const float* wra = Whh_p + row_a * 16;
        const float* wib = Wih_p + row_b * 16;
        const float* wrb = Whh_p + row_b * 16;
#pragma unroll
        for (int m = 0; m < 8; m++) {
            wxa[m] = pack2(wia[2 * m] * sc_a, wia[2 * m + 1] * sc_a);
            wha[m] = pack2(wra[2 * m] * sc_a, wra[2 * m + 1] * sc_a);
            wxb[m] = pack2(wib[2 * m] * sc_b, wib[2 * m + 1] * sc_b);
            whb[m] = pack2(wrb[2 * m] * sc_b, wrb[2 * m + 1] * sc_b);
        }
    }
    const float ba = (bih_p[row_a] + bhh_p[row_a]) * sc_a;
    const float bb = (bih_p[row_b] + bhh_p[row_b]) * sc_b;

    float c = 0.f, h = 0.f;
    __syncthreads();

    // x-part for step 0
    ull xaa, xab;
    {
        const ull* xr = (const ull*)&xs[w * 16];
        ull s0 = pack2(ba, 0.f), s1 = 0ULL, u0 = pack2(bb, 0.f), u1 = 0ULL;
#pragma unroll
        for (int m = 0; m < 8; m += 2) {
            s0 = fma2(wxa[m], xr[m], s0); s1 = fma2(wxa[m + 1], xr[m + 1], s1);
            u0 = fma2(wxb[m], xr[m], u0); u1 = fma2(wxb[m + 1], xr[m + 1], u1);
        }
        xaa = fma2(pack2(1.f, 1.f), s1, s0);
        xab = fma2(pack2(1.f, 1.f), u1, u0);
    }

    for (int t = 0; t < T_LEN; t++) {
        // gather h (lanes 0..15) as 8 f32x2 pairs — independent shfls
        ull hp[8];
#pragma unroll
        for (int m = 0; m < 8; m++) {
            float h0 = __shfl_sync(0xffffffffu, h, 2 * m);
            float h1 = __shfl_sync(0xffffffffu, h, 2 * m + 1);
            hp[m] = pack2(h0, h1);
        }
        ull s0 = xaa, s1 = 0ULL, u0 = xab, u1 = 0ULL;
#pragma unroll
        for (int m = 0; m < 8; m += 2) {
            s0 = fma2(wha[m], hp[m], s0); s1 = fma2(wha[m + 1], hp[m + 1], s1);
            u0 = fma2(whb[m], hp[m], u0); u1 = fma2(whb[m + 1], hp[m + 1], u1);
        }
        float2 A0 = unpack2(s0), A1 = unpack2(s1), B0 = unpack2(u0), B1 = unpack2(u1);
        float pa = (A0.x + A0.y) + (A1.x + A1.y);
        float pb = (B0.x + B0.y) + (B1.x + B1.y);
        float ra = rcpf(1.f + ex2f(-pa));                 // sigmoid (i|f)
        float rb = rcpf(1.f + ex2f(-pb));
        float act_b = hi ? rb : (2.f * rb - 1.f);         // o | tanh(g)
        float fv = __shfl_sync(0xffffffffu, ra, jj + 16);
        float ov = __shfl_sync(0xffffffffu, act_b, jj + 16);
        c = fv * c + ra * act_b;                          // valid on hi==0 lanes
        float th = 2.f * rcpf(1.f + ex2f(-c * (2.f * L2E))) - 1.f;
        h = ov * th;
        if (hi == 0) g_z[(size_t)t * 8192 + b * 16 + jj] = h;

        // shadow: x-part for t+1
        if (t < T_LEN - 1) {
            const ull* xr = (const ull*)&xs[(t + 1) * 128 + w * 16];
            ull a0 = pack2(ba, 0.f), a1 = 0ULL, b0 = pack2(bb, 0.f), b1 = 0ULL;
#pragma unroll
            for (int m = 0; m < 8; m += 2) {
                a0 = fma2(wxa[m], xr[m], a0); a1 = fma2(wxa[m + 1], xr[m + 1], a1);
                b0 = fma2(wxb[m], xr[m], b0); b1 = fma2(wxb[m + 1], xr[m + 1], b1);
            }
            xaa = fma2(pack2(1.f, 1.f), a1, a0);
            xab = fma2(pack2(1.f, 1.f), b1, b0);
        }
    }
}

// ---------------- K4: tensor-core attention + output head, one CTA per t ----------------
// cp double-buffered by tile parity; each warp redundantly reduces column sums
// (conflict-free LDS) and distributes inv via shfl -> ONE syncthreads per tile.
#define HP 20
#define HTP 516
#define OFF_HHI   0
#define OFF_HLO   20480
#define OFF_ZHI   40960
#define OFF_ZLO   61440
#define OFF_HT    81920
#define OFF_CP    114944
#define OFF_CTX   119552
#define OFF_WH    154368
#define OFF_WE    155392
#define OFF_WV    156416
#define ATT_SMEM  156544

__global__ __launch_bounds__(512, 1) void k_attn(
    const float* __restrict__ W_h, const float* __restrict__ W_e,
    const float* __restrict__ W_v, float* __restrict__ out)
{
    extern __shared__ char smc[];
    __nv_bfloat16* hhi = (__nv_bfloat16*)(smc + OFF_HHI);
    __nv_bfloat16* hlo = (__nv_bfloat16*)(smc + OFF_HLO);
    __nv_bfloat16* zhi = (__nv_bfloat16*)(smc + OFF_ZHI);
    __nv_bfloat16* zlo = (__nv_bfloat16*)(smc + OFF_ZLO);
    float* hT   = (float*)(smc + OFF_HT);
    float* cp   = (float*)(smc + OFF_CP);     // 2 x 16 x 36 floats
    float* ctx  = (float*)(smc + OFF_CTX);
    float* sWh  = (float*)(smc + OFF_WH);
    float* sWe  = (float*)(smc + OFF_WE);
    float* sWv  = (float*)(smc + OFF_WV);

    const int t = blockIdx.x, tid = threadIdx.x;
    const int w = tid >> 5, lane = tid & 31;
    const int qr = lane >> 2, qc = lane & 3;
    const float LOG2E = 1.4426950408889634f;

    const float4* hg = (const float4*)(g_h + (size_t)t * 8192);
    const float4* zg = (const float4*)(g_z + (size_t)t * 8192);
#pragma unroll
    for (int it = 0; it < 4; it++) {
        int i = it * 512 + tid;
        int r = i >> 2, d4 = (i & 3) * 4;
        float4 v = hg[i];
        uint32 h01 = packbf(v.x, v.y), h23 = packbf(v.z, v.w);
        *(uint32*)&hhi[r * HP + d4]     = h01;
        *(uint32*)&hhi[r * HP + d4 + 2] = h23;
        *(uint32*)&hlo[r * HP + d4]     = packbf(v.x - bflo(h01), v.y - bfhi(h01));
        *(uint32*)&hlo[r * HP + d4 + 2] = packbf(v.z - bflo(h23), v.w - bfhi(h23));
        hT[(d4 + 0) * HTP + r] = v.x;
        hT[(d4 + 1) * HTP + r] = v.y;
        hT[(d4 + 2) * HTP + r] = v.z;
        hT[(d4 + 3) * HTP + r] = v.w;
        float4 u = zg[i];
        u.x *= LOG2E; u.y *= LOG2E; u.z *= LOG2E; u.w *= LOG2E;
        uint32 z01 = packbf(u.x, u.y), z23 = packbf(u.z, u.w);
        *(uint32*)&zhi[r * HP + d4]     = z01;
        *(uint32*)&zhi[r * HP + d4 + 2] = z23;
        *(uint32*)&zlo[r * HP + d4]     = packbf(u.x - bflo(z01), u.y - bfhi(z01));
        *(uint32*)&zlo[r * HP + d4 + 2] = packbf(u.z - bflo(z23), u.w - bfhi(z23));
    }
    if (tid < 256) { sWh[tid] = W_h[tid]; sWe[tid] = W_e[tid]; }
    if (tid < 16)  sWv[tid] = W_v[tid];
    __syncthreads();

    uint32 Ahh[2][4], Ahl[2][4];
#pragma unroll
    for (int mt = 0; mt < 2; mt++) {
        int row = 32 * w + 16 * mt + qr;
        int base = row * HP + 2 * qc;
        Ahh[mt][0] = *(const uint32*)&hhi[base];
        Ahh[mt][1] = *(const uint32*)&hhi[base + 8 * HP];
        Ahh[mt][2] = *(const uint32*)&hhi[base + 8];
        Ahh[mt][3] = *(const uint32*)&hhi[base + 8 * HP + 8];
        Ahl[mt][0] = *(const uint32*)&hlo[base];
        Ahl[mt][1] = *(const uint32*)&hlo[base + 8 * HP];
        Ahl[mt][2] = *(const uint32*)&hlo[base + 8];
        Ahl[mt][3] = *(const uint32*)&hlo[base + 8 * HP + 8];
    }

    float ctxacc[2][2][4];
#pragma unroll
    for (int mt = 0; mt < 2; mt++)
#pragma unroll
        for (int nt = 0; nt < 2; nt++)
#pragma unroll
            for (int q = 0; q < 4; q++) ctxacc[mt][nt][q] = 0.f;

    for (int tile = 0; tile < 16; tile++) {
        const int c0 = tile * 32;
        float* cpb = cp + (tile & 1) * 576;
        uint32 Aeh[2][2][4], Ael[2][2][4];

#pragma unroll
        for (int nt = 0; nt < 4; nt++) {
            int crow = c0 + 8 * nt + qr;
            int zb = crow * HP + 2 * qc;
            uint32 bzh[2], bzl[2];
            bzh[0] = *(const uint32*)&zhi[zb];
            bzh[1] = *(const uint32*)&zhi[zb + 8];
            bzl[0] = *(const uint32*)&zlo[zb];
            bzl[1] = *(const uint32*)&zlo[zb + 8];
            float P0 = 0.f, P1 = 0.f;
            const int ks = nt >> 1, hf = nt & 1;
#pragma unroll
            for (int mt = 0; mt < 2; mt++) {
                float S[4] = {0.f, 0.f, 0.f, 0.f};
                mma_bf16(S, Ahh[mt], bzh);
                mma_bf16(S, Ahh[mt], bzl);
                mma_bf16(S, Ahl[mt], bzh);
                float e0 = ex2f(S[0]), e1 = ex2f(S[1]), e2 = ex2f(S[2]), e3 = ex2f(S[3]);
                P0 += e0 + e2; P1 += e1 + e3;
                uint32 p01 = packbf(e0, e1), p23 = packbf(e2, e3);
                Aeh[mt][ks][2 * hf]     = p01;
                Aeh[mt][ks][2 * hf + 1] = p23;
                Ael[mt][ks][2 * hf]     = packbf(e0 - bflo(p01), e1 - bfhi(p01));
                Ael[mt][ks][2 * hf + 1] = packbf(e2 - bflo(p23), e3 - bfhi(p23));
            }
            P0 += __shfl_xor_sync(0xffffffffu, P0, 4);
            P0 += __shfl_xor_sync(0xffffffffu, P0, 8);
            P0 += __shfl_xor_sync(0xffffffffu, P0, 16);
            P1 += __shfl_xor_sync(0xffffffffu, P1, 4);
            P1 += __shfl_xor_sync(0xffffffffu, P1, 8);
            P1 += __shfl_xor_sync(0xffffffffu, P1, 16);
            if (qr == 0) {
                cpb[w * 36 + 8 * nt + 2 * qc]     = P0;
                cpb[w * 36 + 8 * nt + 2 * qc + 1] = P1;
            }
        }
        __syncthreads();

        // per-warp redundant column-sum reduction; lane l owns column c0+l
        float ssum = 0.f;
#pragma unroll
        for (int ww = 0; ww < 16; ww++) ssum += cpb[ww * 36 + lane];
        float inv = __fdividef(1.f, ssum);

#pragma unroll
        for (int ks = 0; ks < 2; ks++) {
            int cc = 16 * ks + 2 * qc;
            float i0 = __shfl_sync(0xffffffffu, inv, cc);
            float i1 = __shfl_sync(0xffffffffu, inv, cc + 1);
            float i8 = __shfl_sync(0xffffffffu, inv, cc + 8);
            float i9 = __shfl_sync(0xffffffffu, inv, cc + 9);
#pragma unroll
            for (int nt2 = 0; nt2 < 2; nt2++) {
                int d = 8 * nt2 + qr;
                const float* hr = hT + d * HTP + c0 + cc;
                float v0 = hr[0] * i0, v1 = hr[1] * i1, v8 = hr[8] * i8, v9 = hr[9] * i9;
                uint32 bh[2], bl[2];
                bh[0] = packbf(v0, v1);
                bh[1] = packbf(v8, v9);
                bl[0] = packbf(v0 - bflo(bh[0]), v1 - bfhi(bh[0]));
                bl[1] = packbf(v8 - bflo(bh[1]), v9 - bfhi(bh[1]));
#pragma unroll
                for (int mt = 0; mt < 2; mt++) {
                    mma_bf16(ctxacc[mt][nt2], Aeh[mt][ks], bh);
                    mma_bf16(ctxacc[mt][nt2], Ael[mt][ks], bh);
                    mma_bf16(ctxacc[mt][nt2], Aeh[mt][ks], bl);
                }
            }
        }
    }

#pragma unroll
    for (int mt = 0; mt < 2; mt++)
#pragma unroll
        for (int nt2 = 0; nt2 < 2; nt2++) {
            int row = 32 * w + 16 * mt + qr;
            int col = 8 * nt2 + 2 * qc;
            ctx[row * 17 + col]           = ctxacc[mt][nt2][0];
            ctx[row * 17 + col + 1]       = ctxacc[mt][nt2][1];
            ctx[(row + 8) * 17 + col]     = ctxacc[mt][nt2][2];
            ctx[(row + 8) * 17 + col + 1] = ctxacc[mt][nt2][3];
        }
    __syncthreads();

    {
        int b = tid;
        float hb2[16], cx[16];
        const float4* hp4 = (const float4*)(g_h + (size_t)t * 8192 + b * 16);
#pragma unroll
        for (int q = 0; q < 4; q++) {
            float4 v = hp4[q];
            hb2[4 * q + 0] = v.x; hb2[4 * q + 1] = v.y; hb2[4 * q + 2] = v.z; hb2[4 * q + 3] = v.w;
        }
#pragma unroll
        for (int k = 0; k < 16; k++) cx[k] = ctx[b * 17 + k];
        float pv = 0.f;
#pragma unroll
        for (int r = 0; r < 16; r++) {
            float a = 0.f;
#pragma unroll
            for (int k = 0; k < 16; k++)
                a += sWh[r * 16 + k] * hb2[k] + sWe[r * 16 + k] * cx[k];
            pv += sWv[r] * tanhf_fast(a);
        }
        out[(size_t)t * BATCH + b] = sigf(pv);
    }
}

// ---------------- launch ----------------
extern "C" void kernel_launch(void* const* d_in, const int* in_sizes, int n_in,
                              void* d_out, int out_size)
{
    const float* X     = (const float*)d_in[0];
    const float* Wih_f = (const float*)d_in[1];
    const float* Whh_f = (const float*)d_in[2];
    const float* bih_f = (const float*)d_in[3];
    const float* bhh_f = (const float*)d_in[4];
    const float* Wih_b = (const float*)d_in[5];
    const float* Whh_b = (const float*)d_in[6];
    const float* bih_b = (const float*)d_in[7];
    const float* bhh_b = (const float*)d_in[8];
    const float* Wih_p = (const float*)d_in[9];
    const float* Whh_p = (const float*)d_in[10];
    const float* bih_p = (const float*)d_in[11];
    const float* bhh_p = (const float*)d_in[12];
    const float* W_h   = (const float*)d_in[13];
    const float* W_e   = (const float*)d_in[14];
    const float* W_v   = (const float*)d_in[15];
    float* out = (float*)d_out;

    cudaFuncSetAttribute((const void*)k_attn, cudaFuncAttributeMaxDynamicSharedMemorySize, 160 * 1024);
    cudaFuncSetAttribute((const void*)k_ptrlstm, cudaFuncAttributeMaxDynamicSharedMemorySize, 64 * 1024);

    k_prep<<<dim3(3, 64), 256>>>(Wih_f, Wih_b, bih_f, bhh_f, bih_b, bhh_b);
    k_gemm_xproj<<<(T_LEN * BATCH) / 128, 256>>>(X);
    k_bilstm<<<64, 256>>>(Whh_f, Whh_b);
    k_ptrlstm<<<64, 256, 64 * 1024>>>(Wih_p, Whh_p, bih_p, bhh_p);
    k_attn<<<T_LEN, 512, ATT_SMEM>>>(W_h, W_e, W_v, out);
}

// round 13
// speedup vs baseline: 1.0713x; 1.0285x over previous
#include <cuda_runtime.h>
#include <cuda_bf16.h>

#define T_LEN 128
#define BATCH 512
#define DIN   768

typedef unsigned long long ull;
typedef unsigned int uint32;

// ---------------- scratch (static device arrays; no allocation) ----------------
static __device__ float g_xproj[T_LEN * BATCH * 64];   // bi-LSTM gate pre-activations (x part + bias)
static __device__ float g_h[T_LEN * BATCH * 16];       // concat(h_f, h_b)
static __device__ float g_z[T_LEN * BATCH * 16];       // ptr-LSTM hidden states
static __device__ __nv_bfloat16 g_Wbh[64 * DIN];       // bf16-hi of combined weight, [n][k]
static __device__ __nv_bfloat16 g_Wbl[64 * DIN];       // bf16-lo residual, [n][k]
static __device__ float g_bc[64];                      // combined bias

// ---------------- helpers ----------------
__device__ __forceinline__ float ex2f(float x) {
    float r; asm("ex2.approx.ftz.f32 %0, %1;" : "=f"(r) : "f"(x)); return r;
}
__device__ __forceinline__ float rcpf(float x) {
    float r; asm("rcp.approx.ftz.f32 %0, %1;" : "=f"(r) : "f"(x)); return r;
}
__device__ __forceinline__ float sigf(float x) {
    return __fdividef(1.f, 1.f + __expf(-x));
}
__device__ __forceinline__ float tanhf_fast(float x) {
    float e = __expf(2.f * x);
    return 1.f - __fdividef(2.f, e + 1.f);
}
// f32x2 packed math
__device__ __forceinline__ ull fma2(ull a, ull b, ull c) {
    ull d; asm("fma.rn.f32x2 %0, %1, %2, %3;" : "=l"(d) : "l"(a), "l"(b), "l"(c)); return d;
}
__device__ __forceinline__ ull pack2(float x, float y) {
    ull d; asm("mov.b64 %0, {%1, %2};" : "=l"(d) : "f"(x), "f"(y)); return d;
}
__device__ __forceinline__ float2 unpack2(ull v) {
    float2 r; asm("mov.b64 {%0, %1}, %2;" : "=f"(r.x), "=f"(r.y) : "l"(v)); return r;
}
// pack two f32 -> bf16x2 (first arg -> low half)
__device__ __forceinline__ uint32 packbf(float lo, float hi) {
    uint32 r; asm("cvt.rn.bf16x2.f32 %0, %1, %2;" : "=r"(r) : "f"(hi), "f"(lo)); return r;
}
__device__ __forceinline__ float bflo(uint32 p) { return __uint_as_float(p << 16); }
__device__ __forceinline__ float bfhi(uint32 p) { return __uint_as_float(p & 0xffff0000u); }

__device__ __forceinline__ uint32 smem_u32(const void* p) {
    uint32 a;
    asm("{ .reg .u64 t; cvta.to.shared.u64 t, %1; cvt.u32.u64 %0, t; }" : "=r"(a) : "l"(p));
    return a;
}
__device__ __forceinline__ void ldsm_x4(uint32& r0, uint32& r1, uint32& r2, uint32& r3, uint32 addr) {
    asm volatile("ldmatrix.sync.aligned.m8n8.x4.shared.b16 {%0,%1,%2,%3}, [%4];"
                 : "=r"(r0), "=r"(r1), "=r"(r2), "=r"(r3) : "r"(addr));
}

// bf16 mma m16n8k16, row.col, f32 accumulate
__device__ __forceinline__ void mma_bf16(float* d, const uint32* a, const uint32* b) {
    asm volatile(
        "mma.sync.aligned.m16n8k16.row.col.f32.bf16.bf16.f32 "
        "{%0,%1,%2,%3}, {%4,%5,%6,%7}, {%8,%9}, {%0,%1,%2,%3};"
        : "+f"(d[0]), "+f"(d[1]), "+f"(d[2]), "+f"(d[3])
        : "r"(a[0]), "r"(a[1]), "r"(a[2]), "r"(a[3]), "r"(b[0]), "r"(b[1]));
}

// ---------------- K0: build combined weight, bf16 hi/lo, transposed [n][k] ----------------
__global__ __launch_bounds__(256) void k_prep(
    const float* __restrict__ Wih_f, const float* __restrict__ Wih_b,
    const float* __restrict__ bih_f, const float* __restrict__ bhh_f,
    const float* __restrict__ bih_b, const float* __restrict__ bhh_b)
{
    int n = blockIdx.y;
    int k = blockIdx.x * 256 + threadIdx.x;
    float w = (n < 32) ? Wih_f[n * DIN + k] : Wih_b[(n - 32) * DIN + k];
    __nv_bfloat16 hi = __float2bfloat16_rn(w);
    float res = w - __bfloat162float(hi);
    g_Wbh[n * DIN + k] = hi;
    g_Wbl[n * DIN + k] = __float2bfloat16_rn(res);
    if (blockIdx.x == 0 && blockIdx.y == 0 && threadIdx.x < 64) {
        int i = threadIdx.x;
        g_bc[i] = (i < 32) ? (bih_f[i] + bhh_f[i]) : (bih_b[i - 32] + bhh_b[i - 32]);
    }
}

// ---------------- K1: xproj = X (65536x768) @ Wc (768x64) + bc  (bf16 mma + ldmatrix) ----------------
#define XPITCH 40   // bf16 pitch -> 80-byte rows: 16B-aligned, ldmatrix conflict-free
__global__ __launch_bounds__(256, 2) void k_gemm_xproj(const float* __restrict__ X)
{
    __shared__ alignas(16) __nv_bfloat16 Xh[128 * XPITCH];
    __shared__ alignas(16) __nv_bfloat16 Xl[128 * XPITCH];
    __shared__ alignas(16) __nv_bfloat16 Wh[64 * XPITCH];
    __shared__ alignas(16) __nv_bfloat16 Wl[64 * XPITCH];

    const int tid = threadIdx.x;
    const int rowBase = blockIdx.x * 128;
    const int w = tid >> 5;
    const int lane = tid & 31;
    const int g = lane >> 2;
    const int t4 = lane & 3;

    const int sel = lane >> 3;
    const int rowA = w * 16 + (sel & 1) * 8 + (lane & 7);
    const int colA = (sel >> 1) * 16;
    const int rowB = (sel >> 1) * 8 + (lane & 7);
    const int colB = (sel & 1) * 16;
    const uint32 aHi = smem_u32(Xh) + rowA * 80 + colA;
    const uint32 aLo = smem_u32(Xl) + rowA * 80 + colA;
    const uint32 bHi = smem_u32(Wh) + rowB * 80 + colB;
    const uint32 bLo = smem_u32(Wl) + rowB * 80 + colB;

    float acc[8][4];
#pragma unroll
    for (int nt = 0; nt < 8; nt++)
#pragma unroll
        for (int q = 0; q < 4; q++) acc[nt][q] = 0.f;

    float4 vx[4];
    ull vwh[2], vwl[2];

#pragma unroll
    for (int i = 0; i < 4; i++) {
        int idx = i * 256 + tid;
        int r = idx >> 3, k4 = (idx & 7) * 4;
        vx[i] = *(const float4*)(X + (size_t)(rowBase + r) * DIN + k4);
    }
#pragma unroll
    for (int i = 0; i < 2; i++) {
        int idx = i * 256 + tid;
        int n = idx >> 3, k8 = (idx & 7) * 4;
        vwh[i] = *(const ull*)(g_Wbh + n * DIN + k8);
        vwl[i] = *(const ull*)(g_Wbl + n * DIN + k8);
    }

    for (int c = 0; c < 24; c++) {
#pragma unroll
        for (int i = 0; i < 4; i++) {
            int idx = i * 256 + tid;
            int r = idx >> 3, k4 = (idx & 7) * 4;
            float4 v = vx[i];
            __nv_bfloat16 hx = __float2bfloat16_rn(v.x);
            __nv_bfloat16 hy = __float2bfloat16_rn(v.y);
            __nv_bfloat16 hz = __float2bfloat16_rn(v.z);
            __nv_bfloat16 hw = __float2bfloat16_rn(v.w);
            *(__nv_bfloat162*)&Xh[r * XPITCH + k4 + 0] = __nv_bfloat162(hx, hy);
            *(__nv_bfloat162*)&Xh[r * XPITCH + k4 + 2] = __nv_bfloat162(hz, hw);
            *(__nv_bfloat162*)&Xl[r * XPITCH + k4 + 0] = __nv_bfloat162(
                __float2bfloat16_rn(v.x - __bfloat162float(hx)),
                __float2bfloat16_rn(v.y - __bfloat162float(hy)));
            *(__nv_bfloat162*)&Xl[r * XPITCH + k4 + 2] = __nv_bfloat162(
                __float2bfloat16_rn(v.z - __bfloat162float(hz)),
                __float2bfloat16_rn(v.w - __bfloat162float(hw)));
        }
#pragma unroll
        for (int i = 0; i < 2; i++) {
            int idx = i * 256 + tid;
            int n = idx >> 3, k8 = (idx & 7) * 4;
            *(ull*)&Wh[n * XPITCH + k8] = vwh[i];
            *(ull*)&Wl[n * XPITCH + k8] = vwl[i];
        }
        __syncthreads();

        if (c < 23) {
            int k0 = (c + 1) * 32;
#pragma unroll
            for (int i = 0; i < 4; i++) {
                int idx = i * 256 + tid;
                int r = idx >> 3, k4 = (idx & 7) * 4;
                vx[i] = *(const float4*)(X + (size_t)(rowBase + r) * DIN + k0 + k4);
            }
#pragma unroll
            for (int i = 0; i < 2; i++) {
                int idx = i * 256 + tid;
                int n = idx >> 3, k8 = (idx & 7) * 4;
                vwh[i] = *(const ull*)(g_Wbh + n * DIN + k0 + k8);
                vwl[i] = *(const ull*)(g_Wbl + n * DIN + k0 + k8);
            }
        }

#pragma unroll
        for (int ks = 0; ks < 2; ks++) {
            uint32 ah[4], al[4];
            ldsm_x4(ah[0], ah[1], ah[2], ah[3], aHi + ks * 32);
            ldsm_x4(al[0], al[1], al[2], al[3], aLo + ks * 32);
#pragma unroll
            for (int p = 0; p < 4; p++) {
                uint32 bh[4], bl[4];
                ldsm_x4(bh[0], bh[1], bh[2], bh[3], bHi + p * 1280 + ks * 32);
                ldsm_x4(bl[0], bl[1], bl[2], bl[3], bLo + p * 1280 + ks * 32);
                mma_bf16(acc[2 * p], ah, bh);
                mma_bf16(acc[2 * p], ah, bl);
                mma_bf16(acc[2 * p], al, bh);
                mma_bf16(acc[2 * p + 1], ah, bh + 2);
                mma_bf16(acc[2 * p + 1], ah, bl + 2);
                mma_bf16(acc[2 * p + 1], al, bh + 2);
            }
        }
        __syncthreads();
    }

    const int r0 = rowBase + w * 16 + g;
#pragma unroll
    for (int nt = 0; nt < 8; nt++) {
        int cbase = nt * 8 + 2 * t4;
        float b0 = g_bc[cbase], b1 = g_bc[cbase + 1];
        *(float2*)(g_xproj + (size_t)r0 * 64 + cbase) = make_float2(acc[nt][0] + b0, acc[nt][1] + b1);
        *(float2*)(g_xproj + (size_t)(r0 + 8) * 64 + cbase) = make_float2(acc[nt][2] + b0, acc[nt][3] + b1);
    }
}

// ---------------- K2: bi-LSTM scan — smem h-broadcast (low MIO), 128-thread blocks ----------------
// 16 lanes per (item,dir): rows i|f on hi=0, g|o on hi=1. h broadcast via warp-private
// parity smem buffer: 1 STS + 4 LDS.64 per step (vs 8 shfl).
__global__ __launch_bounds__(128) void k_bilstm(
    const float* __restrict__ Whh_f, const float* __restrict__ Whh_b)
{
    __shared__ float hbuf[2][8][12];

    const int tid = threadIdx.x;
    const int l = tid & 31;
    const int sub = l >> 4;                 // item-dir within warp (0/1)
    const int l16 = l & 15;
    const int jj = l16 & 7, hi = l16 >> 3;
    const int g = (tid >> 5) * 2 + sub;     // 0..7 within block
    const int itemdir = blockIdx.x * 8 + g; // 0..1023
    const int dir = itemdir >> 9;
    const int b = itemdir & 511;
    const float* Whh = dir ? Whh_b : Whh_f;
    const float L2E = 1.4426950408889634f;
    const float sc_a = L2E;
    const float sc_b = hi ? L2E : 2.f * L2E;
    const int row_a = hi * 8 + jj;
    const int row_b = 16 + hi * 8 + jj;
    const int base = sub * 16;

    ull wha[4], whb[4];
#pragma unroll
    for (int m = 0; m < 4; m++) {
        const float* ra_ = Whh + row_a * 8;
        const float* rb_ = Whh + row_b * 8;
        wha[m] = pack2(ra_[2 * m] * sc_a, ra_[2 * m + 1] * sc_a);
        whb[m] = pack2(rb_[2 * m] * sc_b, rb_[2 * m + 1] * sc_b);
    }

    if (hi == 0) hbuf[0][g][jj] = 0.f;
    float c = 0.f, h = 0.f;

    int t0 = dir ? 127 : 0;
    int t1 = dir ? 126 : 1;
    const float* xp0 = g_xproj + ((size_t)t0 * BATCH + b) * 64 + dir * 32;
    const float* xp1 = g_xproj + ((size_t)t1 * BATCH + b) * 64 + dir * 32;
    float na = xp0[row_a] * sc_a, nb = xp0[row_b] * sc_b;
    float ma = xp1[row_a] * sc_a, mb = xp1[row_b] * sc_b;
    __syncthreads();

    for (int s = 0; s < T_LEN; s++) {
        int t = dir ? (127 - s) : s;
        float qa = na, qb = nb;
        na = ma; nb = mb;
        if (s < T_LEN - 2) {
            int tn = dir ? (125 - s) : (s + 2);
            const float* xn = g_xproj + ((size_t)tn * BATCH + b) * 64 + dir * 32;
            ma = xn[row_a] * sc_a; mb = xn[row_b] * sc_b;
        }
        const int p = s & 1;
        ull hp[4];
        const ull* hr = (const ull*)&hbuf[p][g][0];
#pragma unroll
        for (int m = 0; m < 4; m++) hp[m] = hr[m];

        ull s0 = pack2(qa, 0.f), s1 = 0ULL, u0 = pack2(qb, 0.f), u1 = 0ULL;
        s0 = fma2(wha[0], hp[0], s0); s1 = fma2(wha[1], hp[1], s1);
        u0 = fma2(whb[0], hp[0], u0); u1 = fma2(whb[1], hp[1], u1);
        s0 = fma2(wha[2], hp[2], s0); s1 = fma2(wha[3], hp[3], s1);
        u0 = fma2(whb[2], hp[2], u0); u1 = fma2(whb[3], hp[3], u1);
        float2 A0 = unpack2(s0), A1 = unpack2(s1), B0 = unpack2(u0), B1 = unpack2(u1);
        float pa = (A0.x + A0.y) + (A1.x + A1.y);
        float pb = (B0.x + B0.y) + (B1.x + B1.y);
        float ra = rcpf(1.f + ex2f(-pa));                 // sigmoid (i|f)
        float rb = rcpf(1.f + ex2f(-pb));
        float act_b = hi ? rb : (2.f * rb - 1.f);         // o | tanh(g)
        float fv = __shfl_sync(0xffffffffu, ra, base + 8 + jj);
        float ov = __shfl_sync(0xffffffffu, act_b, base + 8 + jj);
        c = fv * c + ra * act_b;                          // valid on hi==0 lanes
        float th = 2.f * rcpf(1.f + ex2f(-c * (2.f * L2E))) - 1.f;
        h = ov * th;
        if (hi == 0) {
            g_h[(size_t)t * 8192 + b * 16 + dir * 8 + jj] = h;
            hbuf[1 - p][g][jj] = h;
        }
        __syncwarp();
    }
}

// ---------------- K3: ptr-LSTM scan — 32 threads/item, smem h-broadcast, x in MUFU shadow ----------------
__global__ __launch_bounds__(128) void k_ptrlstm(
    const float* __restrict__ Wih_p, const float* __restrict__ Whh_p,
    const float* __restrict__ bih_p, const float* __restrict__ bhh_p)
{
    extern __shared__ float xs[];      // 32 KB: [t*64 + item*16 + e]
    __shared__ float hbuf[2][4][20];

    const int tid = threadIdx.x;
    const int w = tid >> 5, l = tid & 31;
    const int jj = l & 15, hi = l >> 4;
    const int bbase = blockIdx.x * 4;
    const int b = bbase + w;

    for (int i = tid; i < 2048; i += 128) {
        int t = i >> 4, rem = i & 15;
        int item = rem >> 2, f4 = rem & 3;
        float4 v = *(const float4*)(g_h + (size_t)t * 8192 + (bbase + item) * 16 + f4 * 4);
        *(float4*)&xs[t * 64 + item * 16 + f4 * 4] = v;
    }

    const float L2E = 1.4426950408889634f;
    const float sc_a = L2E;
    const float sc_b = hi ? L2E : 2.f * L2E;
    const int row_a = hi * 16 + jj;
    const int row_b = 32 + hi * 16 + jj;

    ull wxa[8], wha[8], wxb[8], whb[8];
    {
        const float* wia = Wih_p + row_a * 16;
        const float* wra = Whh_p + row_a * 16;
        const float* wib = Wih_p + row_b * 16;
        const float* wrb = Whh_p + row_b * 16;
#pragma unroll
        for (int m = 0; m < 8; m++) {
            wxa[m] = pack2(wia[2 * m] * sc_a, wia[2 * m + 1] * sc_a);
            wha[m] = pack2(wra[2 * m] * sc_a, wra[2 * m + 1] * sc_a);
            wxb[m] = pack2(wib[2 * m] * sc_b, wib[2 * m + 1] * sc_b);
            whb[m] = pack2(wrb[2 * m] * sc_b, wrb[2 * m + 1] * sc_b);
        }
    }
    const float ba = (bih_p[row_a] + bhh_p[row_a]) * sc_a;
    const float bb = (bih_p[row_b] + bhh_p[row_b]) * sc_b;

    if (hi == 0) hbuf[0][w][jj] = 0.f;
    float c = 0.f;
    __syncthreads();

    // x-part for step 0
    ull xaa, xab;
    {
        const ull* xr = (const ull*)&xs[w * 16];
        ull s0 = pack2(ba, 0.f), s1 = 0ULL, u0 = pack2(bb, 0.f), u1 = 0ULL;
#pragma unroll
        for (int m = 0; m < 8; m += 2) {
            s0 = fma2(wxa[m], xr[m], s0); s1 = fma2(wxa[m + 1], xr[m + 1], s1);
            u0 = fma2(wxb[m], xr[m], u0); u1 = fma2(wxb[m + 1], xr[m + 1], u1);
        }
        xaa = fma2(pack2(1.f, 1.f), s1, s0);
        xab = fma2(pack2(1.f, 1.f), u1, u0);
    }

    for (int t = 0; t < T_LEN; t++) {
        const int p = t & 1;
        // h broadcast: 8 LDS.64 (all lanes read the same warp-private row)
        ull hp[8];
        const ull* hr = (const ull*)&hbuf[p][w][0];
#pragma unroll
        for (int m = 0; m < 8; m++) hp[m] = hr[m];

        ull s0 = xaa, s1 = 0ULL, u0 = xab, u1 = 0ULL;
#pragma unroll
        for (int m = 0; m < 8; m += 2) {
            s0 = fma2(wha[m], hp[m], s0); s1 = fma2(wha[m + 1], hp[m + 1], s1);
            u0 = fma2(whb[m], hp[m], u0); u1 = fma2(whb[m + 1], hp[m + 1], u1);
        }
        float2 A0 = unpack2(s0), A1 = unpack2(s1), B0 = unpack2(u0), B1 = unpack2(u1);
        float pa = (A0.x + A0.y) + (A1.x + A1.y);
        float pb = (B0.x + B0.y) + (B1.x + B1.y);
        float ra = rcpf(1.f + ex2f(-pa));                 // sigmoid (i|f)
        float rb = rcpf(1.f + ex2f(-pb));
        float act_b = hi ? rb : (2.f * rb - 1.f);         // o | tanh(g)
        float fv = __shfl_sync(0xffffffffu, ra, jj + 16);
        float ov = __shfl_sync(0xffffffffu, act_b, jj + 16);
        c = fv * c + ra * act_b;                          // valid on hi==0 lanes
        float th = 2.f * rcpf(1.f + ex2f(-c * (2.f * L2E))) - 1.f;
        float h = ov * th;
        if (hi == 0) {
            g_z[(size_t)t * 8192 + b * 16 + jj] = h;
            hbuf[1 - p][w][jj] = h;
        }

        // shadow: x-part for t+1 (independent of h(t+1))
        if (t < T_LEN - 1) {
            const ull* xr = (const ull*)&xs[(t + 1) * 64 + w * 16];
            ull a0 = pack2(ba, 0.f), a1 = 0ULL, b0 = pack2(bb, 0.f), b1 = 0ULL;
#pragma unroll
            for (int m = 0; m < 8; m += 2) {
                a0 = fma2(wxa[m], xr[m], a0); a1 = fma2(wxa[m + 1], xr[m + 1], a1);
                b0 = fma2(wxb[m], xr[m], b0); b1 = fma2(wxb[m + 1], xr[m + 1], b1);
            }
            xaa = fma2(pack2(1.f, 1.f), a1, a0);
            xab = fma2(pack2(1.f, 1.f), b1, b0);
        }
        __syncwarp();
    }
}

// ---------------- K4: tensor-core attention + output head, one CTA per t ----------------
// cp double-buffered by tile parity; each warp redundantly reduces column sums
// (conflict-free LDS) and distributes inv via shfl -> ONE syncthreads per tile.
#define HP 20
#define HTP 516
#define OFF_HHI   0
#define OFF_HLO   20480
#define OFF_ZHI   40960
#define OFF_ZLO   61440
#define OFF_HT    81920
#define OFF_CP    114944
#define OFF_CTX   119552
#define OFF_WH    154368
#define OFF_WE    155392
#define OFF_WV    156416
#define ATT_SMEM  156544

__global__ __launch_bounds__(512, 1) void k_attn(
    const float* __restrict__ W_h, const float* __restrict__ W_e,
    const float* __restrict__ W_v, float* __restrict__ out)
{
    extern __shared__ char smc[];
    __nv_bfloat16* hhi = (__nv_bfloat16*)(smc + OFF_HHI);
    __nv_bfloat16* hlo = (__nv_bfloat16*)(smc + OFF_HLO);
    __nv_bfloat16* zhi = (__nv_bfloat16*)(smc + OFF_ZHI);
    __nv_bfloat16* zlo = (__nv_bfloat16*)(smc + OFF_ZLO);
    float* hT   = (float*)(smc + OFF_HT);
    float* cp   = (float*)(smc + OFF_CP);     // 2 x 16 x 36 floats
    float* ctx  = (float*)(smc + OFF_CTX);
    float* sWh  = (float*)(smc + OFF_WH);
    float* sWe  = (float*)(smc + OFF_WE);
    float* sWv  = (float*)(smc + OFF_WV);

    const int t = blockIdx.x, tid = threadIdx.x;
    const int w = tid >> 5, lane = tid & 31;
    const int qr = lane >> 2, qc = lane & 3;
    const float LOG2E = 1.4426950408889634f;

    const float4* hg = (const float4*)(g_h + (size_t)t * 8192);
    const float4* zg = (const float4*)(g_z + (size_t)t * 8192);
#pragma unroll
    for (int it = 0; it < 4; it++) {
        int i = it * 512 + tid;
        int r = i >> 2, d4 = (i & 3) * 4;
        float4 v = hg[i];
        uint32 h01 = packbf(v.x, v.y), h23 = packbf(v.z, v.w);
        *(uint32*)&hhi[r * HP + d4]     = h01;
        *(uint32*)&hhi[r * HP + d4 + 2] = h23;
        *(uint32*)&hlo[r * HP + d4]     = packbf(v.x - bflo(h01), v.y - bfhi(h01));
        *(uint32*)&hlo[r * HP + d4 + 2] = packbf(v.z - bflo(h23), v.w - bfhi(h23));
        hT[(d4 + 0) * HTP + r] = v.x;
        hT[(d4 + 1) * HTP + r] = v.y;
        hT[(d4 + 2) * HTP + r] = v.z;
        hT[(d4 + 3) * HTP + r] = v.w;
        float4 u = zg[i];
        u.x *= LOG2E; u.y *= LOG2E; u.z *= LOG2E; u.w *= LOG2E;
        uint32 z01 = packbf(u.x, u.y), z23 = packbf(u.z, u.w);
        *(uint32*)&zhi[r * HP + d4]     = z01;
        *(uint32*)&zhi[r * HP + d4 + 2] = z23;
        *(uint32*)&zlo[r * HP + d4]     = packbf(u.x - bflo(z01), u.y - bfhi(z01));
        *(uint32*)&zlo[r * HP + d4 + 2] = packbf(u.z - bflo(z23), u.w - bfhi(z23));
    }
    if (tid < 256) { sWh[tid] = W_h[tid]; sWe[tid] = W_e[tid]; }
    if (tid < 16)  sWv[tid] = W_v[tid];
    __syncthreads();

    uint32 Ahh[2][4], Ahl[2][4];
#pragma unroll
    for (int mt = 0; mt < 2; mt++) {
        int row = 32 * w + 16 * mt + qr;
        int base = row * HP + 2 * qc;
        Ahh[mt][0] = *(const uint32*)&hhi[base];
        Ahh[mt][1] = *(const uint32*)&hhi[base + 8 * HP];
        Ahh[mt][2] = *(const uint32*)&hhi[base + 8];
        Ahh[mt][3] = *(const uint32*)&hhi[base + 8 * HP + 8];
        Ahl[mt][0] = *(const uint32*)&hlo[base];
        Ahl[mt][1] = *(const uint32*)&hlo[base + 8 * HP];
        Ahl[mt][2] = *(const uint32*)&hlo[base + 8];
        Ahl[mt][3] = *(const uint32*)&hlo[base + 8 * HP + 8];
    }

    float ctxacc[2][2][4];
#pragma unroll
    for (int mt = 0; mt < 2; mt++)
#pragma unroll
        for (int nt = 0; nt < 2; nt++)
#pragma unroll
            for (int q = 0; q < 4; q++) ctxacc[mt][nt][q] = 0.f;

    for (int tile = 0; tile < 16; tile++) {
        const int c0 = tile * 32;
        float* cpb = cp + (tile & 1) * 576;
        uint32 Aeh[2][2][4], Ael[2][2][4];

#pragma unroll
        for (int nt = 0; nt < 4; nt++) {
            int crow = c0 + 8 * nt + qr;
            int zb = crow * HP + 2 * qc;
            uint32 bzh[2], bzl[2];
            bzh[0] = *(const uint32*)&zhi[zb];
            bzh[1] = *(const uint32*)&zhi[zb + 8];
            bzl[0] = *(const uint32*)&zlo[zb];
            bzl[1] = *(const uint32*)&zlo[zb + 8];
            float P0 = 0.f, P1 = 0.f;
            const int ks = nt >> 1, hf = nt & 1;
#pragma unroll
            for (int mt = 0; mt < 2; mt++) {
                float S[4] = {0.f, 0.f, 0.f, 0.f};
                mma_bf16(S, Ahh[mt], bzh);
                mma_bf16(S, Ahh[mt], bzl);
                mma_bf16(S, Ahl[mt], bzh);
                float e0 = ex2f(S[0]), e1 = ex2f(S[1]), e2 = ex2f(S[2]), e3 = ex2f(S[3]);
                P0 += e0 + e2; P1 += e1 + e3;
                uint32 p01 = packbf(e0, e1), p23 = packbf(e2, e3);
                Aeh[mt][ks][2 * hf]     = p01;
                Aeh[mt][ks][2 * hf + 1] = p23;
                Ael[mt][ks][2 * hf]     = packbf(e0 - bflo(p01), e1 - bfhi(p01));
                Ael[mt][ks][2 * hf + 1] = packbf(e2 - bflo(p23), e3 - bfhi(p23));
            }
            P0 += __shfl_xor_sync(0xffffffffu, P0, 4);
            P0 += __shfl_xor_sync(0xffffffffu, P0, 8);
            P0 += __shfl_xor_sync(0xffffffffu, P0, 16);
            P1 += __shfl_xor_sync(0xffffffffu, P1, 4);
            P1 += __shfl_xor_sync(0xffffffffu, P1, 8);
            P1 += __shfl_xor_sync(0xffffffffu, P1, 16);
            if (qr == 0) {
                cpb[w * 36 + 8 * nt + 2 * qc]     = P0;
                cpb[w * 36 + 8 * nt + 2 * qc + 1] = P1;
            }
        }
        __syncthreads();

        // per-warp redundant column-sum reduction; lane l owns column c0+l
        float ssum = 0.f;
#pragma unroll
        for (int ww = 0; ww < 16; ww++) ssum += cpb[ww * 36 + lane];
        float inv = __fdividef(1.f, ssum);

#pragma unroll
        for (int ks = 0; ks < 2; ks++) {
            int cc = 16 * ks + 2 * qc;
            float i0 = __shfl_sync(0xffffffffu, inv, cc);
            float i1 = __shfl_sync(0xffffffffu, inv, cc + 1);
            float i8 = __shfl_sync(0xffffffffu, inv, cc + 8);
            float i9 = __shfl_sync(0xffffffffu, inv, cc + 9);
#pragma unroll
            for (int nt2 = 0; nt2 < 2; nt2++) {
                int d = 8 * nt2 + qr;
                const float* hr = hT + d * HTP + c0 + cc;
                float v0 = hr[0] * i0, v1 = hr[1] * i1, v8 = hr[8] * i8, v9 = hr[9] * i9;
                uint32 bh[2], bl[2];
                bh[0] = packbf(v0, v1);
                bh[1] = packbf(v8, v9);
                bl[0] = packbf(v0 - bflo(bh[0]), v1 - bfhi(bh[0]));
                bl[1] = packbf(v8 - bflo(bh[1]), v9 - bfhi(bh[1]));
#pragma unroll
                for (int mt = 0; mt < 2; mt++) {
                    mma_bf16(ctxacc[mt][nt2], Aeh[mt][ks], bh);
                    mma_bf16(ctxacc[mt][nt2], Ael[mt][ks], bh);
                    mma_bf16(ctxacc[mt][nt2], Aeh[mt][ks], bl);
                }
            }
        }
    }

#pragma unroll
    for (int mt = 0; mt < 2; mt++)
#pragma unroll
        for (int nt2 = 0; nt2 < 2; nt2++) {
            int row = 32 * w + 16 * mt + qr;
            int col = 8 * nt2 + 2 * qc;
            ctx[row * 17 + col]           = ctxacc[mt][nt2][0];
            ctx[row * 17 + col + 1]       = ctxacc[mt][nt2][1];
            ctx[(row + 8) * 17 + col]     = ctxacc[mt][nt2][2];
            ctx[(row + 8) * 17 + col + 1] = ctxacc[mt][nt2][3];
        }
    __syncthreads();

    {
        int b = tid;
        float hb2[16], cx[16];
        const float4* hp4 = (const float4*)(g_h + (size_t)t * 8192 + b * 16);
#pragma unroll
        for (int q = 0; q < 4; q++) {
            float4 v = hp4[q];
            hb2[4 * q + 0] = v.x; hb2[4 * q + 1] = v.y; hb2[4 * q + 2] = v.z; hb2[4 * q + 3] = v.w;
        }
#pragma unroll
        for (int k = 0; k < 16; k++) cx[k] = ctx[b * 17 + k];
        float pv = 0.f;
#pragma unroll
        for (int r = 0; r < 16; r++) {
            float a = 0.f;
#pragma unroll
            for (int k = 0; k < 16; k++)
                a += sWh[r * 16 + k] * hb2[k] + sWe[r * 16 + k] * cx[k];
            pv += sWv[r] * tanhf_fast(a);
        }
        out[(size_t)t * BATCH + b] = sigf(pv);
    }
}

// ---------------- launch ----------------
extern "C" void kernel_launch(void* const* d_in, const int* in_sizes, int n_in,
                              void* d_out, int out_size)
{
    const float* X     = (const float*)d_in[0];
    const float* Wih_f = (const float*)d_in[1];
    const float* Whh_f = (const float*)d_in[2];
    const float* bih_f = (const float*)d_in[3];
    const float* bhh_f = (const float*)d_in[4];
    const float* Wih_b = (const float*)d_in[5];
    const float* Whh_b = (const float*)d_in[6];
    const float* bih_b = (const float*)d_in[7];
    const float* bhh_b = (const float*)d_in[8];
    const float* Wih_p = (const float*)d_in[9];
    const float* Whh_p = (const float*)d_in[10];
    const float* bih_p = (const float*)d_in[11];
    const float* bhh_p = (const float*)d_in[12];
    const float* W_h   = (const float*)d_in[13];
    const float* W_e   = (const float*)d_in[14];
    const float* W_v   = (const float*)d_in[15];
    float* out = (float*)d_out;

    cudaFuncSetAttribute((const void*)k_attn, cudaFuncAttributeMaxDynamicSharedMemorySize, 160 * 1024);

    k_prep<<<dim3(3, 64), 256>>>(Wih_f, Wih_b, bih_f, bhh_f, bih_b, bhh_b);
    k_gemm_xproj<<<(T_LEN * BATCH) / 128, 256>>>(X);
    k_bilstm<<<128, 128>>>(Whh_f, Whh_b);
    k_ptrlstm<<<128, 128, 32 * 1024>>>(Wih_p, Whh_p, bih_p, bhh_p);
    k_attn<<<T_LEN, 512, ATT_SMEM>>>(W_h, W_e, W_v, out);
}